// round 8
// baseline (speedup 1.0000x reference)
#include <cuda_runtime.h>
#include <cuda_bf16.h>
#include <cuda.h>
#include <cstdint>
#include <cstddef>

// ===================== problem constants =====================
#define TOKENS 4096
#define HID    1024
#define NEXP   8
#define GUP    2048
#define KTOT   8192          // NEXP*1024

// ===================== GEMM tiling =====================
#define BM     128
#define BN     256
#define BK     32
#define THREADS 512          // 16 warps: 2 (M) x 8 (N), warp tile 64x32

#define A_BYTES   16384      // 128 x 32 x 4
#define B_BYTES   32768      // 32 x 256 x 4
#define STG_BYTES (A_BYTES + B_BYTES)   // 49152
#define SMEM_MBAR 0
#define SMEM_DATA 1024
#define SMEM_TOTAL (SMEM_DATA + 4*STG_BYTES)   // 197632

// ===================== device scratch =====================
__device__ __align__(1024) float g_ACT  [(size_t)TOKENS*KTOT];  // 128 MB (tf32-rounded)
__device__ __align__(1024) float g_BIAS2[(size_t)TOKENS*HID];   // 16 MB
__device__ __align__(1024) float g_XR   [(size_t)TOKENS*HID];   // 16 MB (tf32-rounded X)
__device__ __align__(1024) float g_W1R  [(size_t)NEXP*HID*GUP]; // 64 MB
__device__ __align__(1024) float g_W2R  [(size_t)KTOT*HID];     // 32 MB

// ===================== PTX helpers =====================
__device__ __forceinline__ uint32_t smem_u32(const void* p) {
    uint32_t a;
    asm("{ .reg .u64 t; cvta.to.shared.u64 t, %1; cvt.u32.u64 %0, t; }" : "=r"(a) : "l"(p));
    return a;
}
__device__ __forceinline__ float tf32_rn(float x) {
    uint32_t u;
    asm("cvt.rna.tf32.f32 %0, %1;" : "=r"(u) : "f"(x));
    return __uint_as_float(u);
}
__device__ __forceinline__ void mma8(float* c, const uint32_t* a, const uint32_t* b) {
    asm volatile(
        "mma.sync.aligned.m16n8k8.row.col.f32.tf32.tf32.f32 "
        "{%0,%1,%2,%3}, {%4,%5,%6,%7}, {%8,%9}, {%0,%1,%2,%3};"
        : "+f"(c[0]), "+f"(c[1]), "+f"(c[2]), "+f"(c[3])
        : "r"(a[0]), "r"(a[1]), "r"(a[2]), "r"(a[3]), "r"(b[0]), "r"(b[1]));
}
#define LDS32(x, addr) \
    asm volatile("ld.shared.b32 %0, [%1];" : "=r"(x) : "r"(addr))

#define MBAR_INIT(addr, cnt) \
    asm volatile("mbarrier.init.shared.b64 [%0], %1;" :: "r"((uint32_t)(addr)), "r"((uint32_t)(cnt)) : "memory")
#define MBAR_EXPECT_TX(addr, bytes) \
    asm volatile("mbarrier.arrive.expect_tx.shared.b64 _, [%0], %1;" :: "r"((uint32_t)(addr)), "r"((uint32_t)(bytes)) : "memory")

#define MBAR_WAIT(addr, parity) do {                                                    \
    uint32_t _m = (uint32_t)(addr), _p = (uint32_t)(parity), _d;                        \
    asm volatile("{\n\t.reg .pred p;\n\t"                                               \
        "mbarrier.try_wait.parity.acquire.cta.shared::cta.b64 p, [%1], %2;\n\t"         \
        "selp.b32 %0, 1, 0, p;\n\t}" : "=r"(_d) : "r"(_m), "r"(_p) : "memory");         \
    if (!_d) {                                                                          \
        asm volatile("{\n\t.reg .pred P1;\n\t"                                          \
            "WLA_%=:\n\t"                                                               \
            "mbarrier.try_wait.parity.acquire.cta.shared::cta.b64 P1, [%0], %1, 0x989680;\n\t" \
            "@P1 bra.uni WDA_%=;\n\t"                                                   \
            "bra.uni WLA_%=;\n\t"                                                       \
            "WDA_%=:\n\t}" :: "r"(_m), "r"(_p) : "memory");                             \
    }                                                                                   \
} while (0)

#define TMA2D(smem_addr, tmap, cx, cy, mbar) \
    asm volatile("cp.async.bulk.tensor.2d.shared::cta.global.tile.mbarrier::complete_tx::bytes " \
        "[%0], [%1, {%2, %3}], [%4];" \
        :: "r"((uint32_t)(smem_addr)), "l"(tmap), "r"((int32_t)(cx)), "r"((int32_t)(cy)), \
           "r"((uint32_t)(mbar)) : "memory")
#define TMA3D(smem_addr, tmap, cx, cy, cz, mbar) \
    asm volatile("cp.async.bulk.tensor.3d.shared::cta.global.tile.mbarrier::complete_tx::bytes " \
        "[%0], [%1, {%2, %3, %4}], [%5];" \
        :: "r"((uint32_t)(smem_addr)), "l"(tmap), "r"((int32_t)(cx)), "r"((int32_t)(cy)), \
           "r"((int32_t)(cz)), "r"((uint32_t)(mbar)) : "memory")

// ===================== fused GEMM kernel =====================
// EPI=1: GEMM1 (Xr @ W1r, K=1024, B 3D over experts) -> act epilogue -> ACT (rounded)
// EPI=2: GEMM2 (ACT @ W2r, K=8192, B 2D)             -> + BIAS2 -> out
template <int KT, bool B3D, int EPI>
__global__ void __launch_bounds__(THREADS, 1)
gemm_kernel(const __grid_constant__ CUtensorMap mA,
            const __grid_constant__ CUtensorMap mB,
            const float* __restrict__ b1,      // [8][2048]    (EPI=1)
            const float* __restrict__ rw,      // [4096][8]    (EPI=1)
            const float* __restrict__ bias2,   // [4096][1024] (EPI=2)
            float* __restrict__ outp)
{
    extern __shared__ __align__(1024) char smem[];
    uint32_t sb = smem_u32(smem);

    const int tid  = threadIdx.x;
    const int lane = tid & 31;
    const int w    = tid >> 5;          // 0..15
    const int mw   = (w >> 3) * 64;     // warp M offset (0,64)
    const int nw   = (w & 7) * 32;      // warp N offset (0..224)
    const int gid  = lane >> 2;         // 0..7
    const int tig  = lane & 3;          // 0..3

    const int m0    = blockIdx.x * BM;
    const int nglob = blockIdx.y * BN;
    int e = 0, nb;
    if (B3D) { e = nglob >> 11; nb = nglob & (GUP - 1); }
    else     { nb = nglob; }

    if (tid == 0) {
        #pragma unroll
        for (int i = 0; i < 4; i++) MBAR_INIT(sb + SMEM_MBAR + i * 8, 1);
    }
    __syncthreads();

    auto issue = [&](int s) {
        int b = s & 3, k0 = s * BK;
        uint32_t mb  = sb + SMEM_MBAR + b * 8;
        uint32_t dst = sb + SMEM_DATA + b * STG_BYTES;
        MBAR_EXPECT_TX(mb, STG_BYTES);
        TMA2D(dst, &mA, k0, m0, mb);                       // A tile [128m x 32k], SW128
        #pragma unroll
        for (int c = 0; c < 8; c++) {                      // B tile in 8 [32k x 32n] chunks
            if (B3D) TMA3D(dst + A_BYTES + c * 4096, &mB, nb + c * 32, k0, e, mb);
            else     TMA2D(dst + A_BYTES + c * 4096, &mB, nb + c * 32, k0, mb);
        }
    };

    if (tid == 0) { issue(0); issue(1); issue(2); }

    float acc[4][4][4];
    #pragma unroll
    for (int i = 0; i < 4; i++)
        #pragma unroll
        for (int j = 0; j < 4; j++)
            #pragma unroll
            for (int r = 0; r < 4; r++) acc[i][j][r] = 0.0f;

    const uint32_t aXor = (uint32_t)gid << 4;   // A swizzle xor (row&7 == gid for all frags)

    #pragma unroll 1
    for (int kt = 0; kt < KT; kt++) {
        int b = kt & 3;
        MBAR_WAIT(sb + SMEM_MBAR + b * 8, (kt >> 2) & 1);
        __syncthreads();                          // prior stage fully consumed by all threads
        if (tid == 0 && kt + 3 < KT) issue(kt + 3);

        uint32_t sA = sb + SMEM_DATA + b * STG_BYTES;
        uint32_t sB = sA + A_BYTES;

        #pragma unroll
        for (int ks = 0; ks < 4; ks++) {
            const int kk = ks * 8;
            const uint32_t kx0 = ((uint32_t)((kk + tig) * 4)) ^ aXor;
            const uint32_t kx1 = ((uint32_t)((kk + tig + 4) * 4)) ^ aXor;
            uint32_t a[4][4];
            #pragma unroll
            for (int mf = 0; mf < 4; mf++) {
                uint32_t base0 = sA + (uint32_t)((mw + mf * 16 + gid) * 128);
                uint32_t base1 = base0 + 8 * 128;
                LDS32(a[mf][0], base0 + kx0);
                LDS32(a[mf][1], base1 + kx0);
                LDS32(a[mf][2], base0 + kx1);
                LDS32(a[mf][3], base1 + kx1);
            }
            uint32_t bf[4][2];
            #pragma unroll
            for (int nf = 0; nf < 4; nf++) {
                int n  = nw + nf * 8 + gid;
                int c  = n >> 5, nn = n & 31;
                uint32_t x0 = ((uint32_t)(nn * 4)) ^ ((uint32_t)tig << 4);
                uint32_t x1 = ((uint32_t)(nn * 4)) ^ (((uint32_t)tig + 4u) << 4);
                uint32_t cb = sB + (uint32_t)(c * 4096);
                LDS32(bf[nf][0], cb + (uint32_t)((kk + tig) * 128) + x0);
                LDS32(bf[nf][1], cb + (uint32_t)((kk + tig + 4) * 128) + x1);
            }
            #pragma unroll
            for (int mf = 0; mf < 4; mf++)
                #pragma unroll
                for (int nf = 0; nf < 4; nf++)
                    mma8(acc[mf][nf], a[mf], bf[nf]);
        }
    }

    // ===================== epilogue =====================
    if (EPI == 1) {
        #pragma unroll
        for (int mf = 0; mf < 4; mf++) {
            #pragma unroll
            for (int h = 0; h < 2; h++) {
                int t = m0 + mw + mf * 16 + h * 8 + gid;
                float rwv = rw[t * NEXP + e];
                float* actp = outp + (size_t)t * KTOT + e * 1024;
                #pragma unroll
                for (int nf = 0; nf < 4; nf++) {
                    int gcol = nb + nw + nf * 8 + 2 * tig;   // even = gate, odd = up
                    float2 bv = *(const float2*)(b1 + e * GUP + gcol);
                    float g = acc[mf][nf][h * 2 + 0] + bv.x;
                    float u = acc[mf][nf][h * 2 + 1] + bv.y;
                    g = fminf(g, 7.0f);
                    u = fminf(fmaxf(u, -7.0f), 7.0f);
                    float glu = g / (1.0f + __expf(-1.702f * g));
                    actp[gcol >> 1] = tf32_rn((u + 1.0f) * glu * rwv);
                }
            }
        }
    } else {
        #pragma unroll
        for (int mf = 0; mf < 4; mf++) {
            #pragma unroll
            for (int h = 0; h < 2; h++) {
                int t = m0 + mw + mf * 16 + h * 8 + gid;
                const float* bp = bias2 + (size_t)t * HID + nglob;
                float* op = outp + (size_t)t * HID + nglob;
                #pragma unroll
                for (int nf = 0; nf < 4; nf++) {
                    int n = nw + nf * 8 + 2 * tig;
                    float2 bv = *(const float2*)(bp + n);
                    float2 ov;
                    ov.x = acc[mf][nf][h * 2 + 0] + bv.x;
                    ov.y = acc[mf][nf][h * 2 + 1] + bv.y;
                    *(float2*)(op + n) = ov;
                }
            }
        }
    }
}

// ===================== prep kernels =====================
// One kernel rounds X, W1, W2 (range-dispatched) to tf32 bit patterns.
#define N4_X  (TOKENS*HID/4)                 // 1,048,576
#define N4_W1 (NEXP*HID*GUP/4)               // 4,194,304
#define N4_W2 (KTOT*HID/4)                   // 2,097,152
__global__ void round_all_kernel(const float4* __restrict__ X,  float4* __restrict__ XR,
                                 const float4* __restrict__ W1, float4* __restrict__ W1R,
                                 const float4* __restrict__ W2, float4* __restrict__ W2R) {
    int i = blockIdx.x * 256 + threadIdx.x;
    const float4* src; float4* dst; int j;
    if (i < N4_X)              { src = X;  dst = XR;  j = i; }
    else if (i < N4_X + N4_W1) { src = W1; dst = W1R; j = i - N4_X; }
    else                       { src = W2; dst = W2R; j = i - N4_X - N4_W1; }
    float4 v = src[j];
    v.x = tf32_rn(v.x); v.y = tf32_rn(v.y); v.z = tf32_rn(v.z); v.w = tf32_rn(v.w);
    dst[j] = v;
}

__global__ void bias2_kernel(const float* __restrict__ rw,
                             const float* __restrict__ b2,
                             float* __restrict__ bias2) {
    int h = blockIdx.x * 256 + threadIdx.x;
    int t = blockIdx.y;
    float s = 0.0f;
    #pragma unroll
    for (int e = 0; e < NEXP; e++) s += rw[t * NEXP + e] * b2[e * HID + h];
    bias2[(size_t)t * HID + h] = s;
}

// ===================== host side =====================
typedef CUresult (CUDAAPI *PFN_encodeTiled)(
    CUtensorMap*, CUtensorMapDataType, cuuint32_t, void*,
    const cuuint64_t*, const cuuint64_t*, const cuuint32_t*, const cuuint32_t*,
    CUtensorMapInterleave, CUtensorMapSwizzle, CUtensorMapL2promotion, CUtensorMapFloatOOBfill);

static PFN_encodeTiled get_encode_fn() {
    void* fp = nullptr;
    cudaDriverEntryPointQueryResult qr;
#if CUDART_VERSION >= 12050
    cudaGetDriverEntryPointByVersion("cuTensorMapEncodeTiled", &fp, 12000, cudaEnableDefault, &qr);
#else
    cudaGetDriverEntryPoint("cuTensorMapEncodeTiled", &fp, cudaEnableDefault, &qr);
#endif
    return (PFN_encodeTiled)fp;
}

static CUtensorMap make_map(PFN_encodeTiled enc, void* p, int nd,
                            uint64_t d0, uint64_t d1, uint64_t d2,
                            uint32_t b0, uint32_t b1) {
    CUtensorMap m;
    cuuint64_t dims[3]    = {d0, d1, d2};
    cuuint64_t strides[2] = {d0 * 4, d0 * d1 * 4};
    cuuint32_t box[3]     = {b0, b1, 1};
    cuuint32_t es[3]      = {1, 1, 1};
    enc(&m, CU_TENSOR_MAP_DATA_TYPE_FLOAT32, nd, p, dims, strides, box, es,
        CU_TENSOR_MAP_INTERLEAVE_NONE, CU_TENSOR_MAP_SWIZZLE_128B,
        CU_TENSOR_MAP_L2_PROMOTION_L2_128B, CU_TENSOR_MAP_FLOAT_OOB_FILL_NONE);
    return m;
}

extern "C" void kernel_launch(void* const* d_in, const int* in_sizes, int n_in,
                              void* d_out, int out_size) {
    const float* X  = (const float*)d_in[0];  // [4096][1024]
    const float* RW = (const float*)d_in[1];  // [4096][8]
    const float* W1 = (const float*)d_in[2];  // [8][1024][2048]
    const float* B1 = (const float*)d_in[3];  // [8][2048]
    const float* W2 = (const float*)d_in[4];  // [8][1024][1024]
    const float* B2 = (const float*)d_in[5];  // [8][1024]
    float* OUT = (float*)d_out;

    float *ACT, *BIAS2, *XR, *W1R, *W2R;
    cudaGetSymbolAddress((void**)&ACT,   g_ACT);
    cudaGetSymbolAddress((void**)&BIAS2, g_BIAS2);
    cudaGetSymbolAddress((void**)&XR,    g_XR);
    cudaGetSymbolAddress((void**)&W1R,   g_W1R);
    cudaGetSymbolAddress((void**)&W2R,   g_W2R);

    PFN_encodeTiled enc = get_encode_fn();
    CUtensorMap mA1 = make_map(enc, XR,  2, HID,  TOKENS, 1,    BK, BM);
    CUtensorMap mB1 = make_map(enc, W1R, 3, GUP,  HID,    NEXP, 32, BK);
    CUtensorMap mA2 = make_map(enc, ACT, 2, KTOT, TOKENS, 1,    BK, BM);
    CUtensorMap mB2 = make_map(enc, W2R, 2, HID,  KTOT,   1,    32, BK);

    cudaFuncSetAttribute((const void*)gemm_kernel<HID/BK,  true,  1>,
                         cudaFuncAttributeMaxDynamicSharedMemorySize, SMEM_TOTAL);
    cudaFuncSetAttribute((const void*)gemm_kernel<KTOT/BK, false, 2>,
                         cudaFuncAttributeMaxDynamicSharedMemorySize, SMEM_TOTAL);

    // prep: tf32 rounding (fused) + bias2
    round_all_kernel<<<(N4_X + N4_W1 + N4_W2) / 256, 256>>>(
        (const float4*)X,  (float4*)XR,
        (const float4*)W1, (float4*)W1R,
        (const float4*)W2, (float4*)W2R);
    bias2_kernel<<<dim3(HID / 256, TOKENS), 256>>>(RW, B2, BIAS2);

    // GEMM1: [4096 x 16384], K=1024
    gemm_kernel<HID/BK, true, 1><<<dim3(TOKENS / BM, (NEXP * GUP) / BN), THREADS, SMEM_TOTAL>>>(
        mA1, mB1, B1, RW, nullptr, ACT);

    // GEMM2: [4096 x 1024], K=8192
    gemm_kernel<KTOT/BK, false, 2><<<dim3(TOKENS / BM, HID / BN), THREADS, SMEM_TOTAL>>>(
        mA2, mB2, nullptr, nullptr, BIAS2, OUT);
}

// round 11
// speedup vs baseline: 1.1566x; 1.1566x over previous
#include <cuda_runtime.h>
#include <cuda_bf16.h>
#include <cuda.h>
#include <cstdint>
#include <cstddef>

// ===================== problem constants =====================
#define TOKENS 4096
#define HID    1024
#define NEXP   8
#define GUP    2048
#define KTOT   8192          // NEXP*1024

// ===================== GEMM tiling =====================
#define BM     128
#define BN     256
#define BK     32
#define THREADS 256          // 8 warps: 2 (M) x 4 (N), warp tile 64x64

#define A_BYTES   16384      // 128 rows x 128B (32k)
#define B_BYTES   32768      // 256 n-rows x 128B (32k)   [N-major!]
#define STG_BYTES (A_BYTES + B_BYTES)   // 49152
#define SMEM_MBAR 0
#define SMEM_DATA 1024
#define SMEM_TOTAL (SMEM_DATA + 4*STG_BYTES)   // 197632

// ===================== device scratch =====================
__device__ __align__(1024) float g_ACT  [(size_t)TOKENS*KTOT];  // 128 MB (tf32-rounded)
__device__ __align__(1024) float g_BIAS2[(size_t)TOKENS*HID];   // 16 MB
__device__ __align__(1024) float g_XR   [(size_t)TOKENS*HID];   // 16 MB (tf32-rounded X)
__device__ __align__(1024) float g_W1T  [(size_t)NEXP*GUP*HID]; // 64 MB  [e][g][h] (n-major)
__device__ __align__(1024) float g_W2T  [(size_t)HID*KTOT];     // 32 MB  [h][e*1024+d] (n-major)

// ===================== PTX helpers =====================
__device__ __forceinline__ uint32_t smem_u32(const void* p) {
    uint32_t a;
    asm("{ .reg .u64 t; cvta.to.shared.u64 t, %1; cvt.u32.u64 %0, t; }" : "=r"(a) : "l"(p));
    return a;
}
__device__ __forceinline__ float tf32_rn(float x) {
    uint32_t u;
    asm("cvt.rna.tf32.f32 %0, %1;" : "=r"(u) : "f"(x));
    return __uint_as_float(u);
}
__device__ __forceinline__ void mma8(float* c, const uint32_t* a, const uint32_t* b) {
    asm volatile(
        "mma.sync.aligned.m16n8k8.row.col.f32.tf32.tf32.f32 "
        "{%0,%1,%2,%3}, {%4,%5,%6,%7}, {%8,%9}, {%0,%1,%2,%3};"
        : "+f"(c[0]), "+f"(c[1]), "+f"(c[2]), "+f"(c[3])
        : "r"(a[0]), "r"(a[1]), "r"(a[2]), "r"(a[3]), "r"(b[0]), "r"(b[1]));
}
#define LDSM4(r0, r1, r2, r3, addr) \
    asm volatile("ldmatrix.sync.aligned.m8n8.x4.shared.b16 {%0,%1,%2,%3}, [%4];" \
        : "=r"(r0), "=r"(r1), "=r"(r2), "=r"(r3) : "r"(addr))

#define MBAR_INIT(addr, cnt) \
    asm volatile("mbarrier.init.shared.b64 [%0], %1;" :: "r"((uint32_t)(addr)), "r"((uint32_t)(cnt)) : "memory")
#define MBAR_EXPECT_TX(addr, bytes) \
    asm volatile("mbarrier.arrive.expect_tx.shared.b64 _, [%0], %1;" :: "r"((uint32_t)(addr)), "r"((uint32_t)(bytes)) : "memory")

#define MBAR_WAIT(addr, parity) do {                                                    \
    uint32_t _m = (uint32_t)(addr), _p = (uint32_t)(parity), _d;                        \
    asm volatile("{\n\t.reg .pred p;\n\t"                                               \
        "mbarrier.try_wait.parity.acquire.cta.shared::cta.b64 p, [%1], %2;\n\t"         \
        "selp.b32 %0, 1, 0, p;\n\t}" : "=r"(_d) : "r"(_m), "r"(_p) : "memory");         \
    if (!_d) {                                                                          \
        asm volatile("{\n\t.reg .pred P1;\n\t"                                          \
            "WLA_%=:\n\t"                                                               \
            "mbarrier.try_wait.parity.acquire.cta.shared::cta.b64 P1, [%0], %1, 0x989680;\n\t" \
            "@P1 bra.uni WDA_%=;\n\t"                                                   \
            "bra.uni WLA_%=;\n\t"                                                       \
            "WDA_%=:\n\t}" :: "r"(_m), "r"(_p) : "memory");                             \
    }                                                                                   \
} while (0)

#define TMA2D(smem_addr, tmap, cx, cy, mbar) \
    asm volatile("cp.async.bulk.tensor.2d.shared::cta.global.tile.mbarrier::complete_tx::bytes " \
        "[%0], [%1, {%2, %3}], [%4];" \
        :: "r"((uint32_t)(smem_addr)), "l"(tmap), "r"((int32_t)(cx)), "r"((int32_t)(cy)), \
           "r"((uint32_t)(mbar)) : "memory")
#define TMA3D(smem_addr, tmap, cx, cy, cz, mbar) \
    asm volatile("cp.async.bulk.tensor.3d.shared::cta.global.tile.mbarrier::complete_tx::bytes " \
        "[%0], [%1, {%2, %3, %4}], [%5];" \
        :: "r"((uint32_t)(smem_addr)), "l"(tmap), "r"((int32_t)(cx)), "r"((int32_t)(cy)), \
           "r"((int32_t)(cz)), "r"((uint32_t)(mbar)) : "memory")

// ===================== fused GEMM kernel =====================
// A smem: [128 m-rows][32 k], 128B rows, SW128.
// B smem: [256 n-rows][32 k], 128B rows, SW128 (N-MAJOR -> natural ldmatrix B frag).
// EPI=1: GEMM1 -> act epilogue -> ACT (rounded). EPI=2: GEMM2 -> + BIAS2 -> out.
template <int KT, bool B3D, int EPI>
__global__ void __launch_bounds__(THREADS, 1)
gemm_kernel(const __grid_constant__ CUtensorMap mA,
            const __grid_constant__ CUtensorMap mB,
            const float* __restrict__ b1,      // [8][2048]    (EPI=1)
            const float* __restrict__ rw,      // [4096][8]    (EPI=1)
            const float* __restrict__ bias2,   // [4096][1024] (EPI=2)
            float* __restrict__ outp)
{
    extern __shared__ __align__(1024) char smem[];
    uint32_t sb = smem_u32(smem);

    const int tid  = threadIdx.x;
    const int lane = tid & 31;
    const int w    = tid >> 5;          // 0..7
    const int mw   = (w >> 2) * 64;     // warp M offset (0,64)
    const int nw   = (w & 3) * 64;      // warp N offset (0,64,128,192)
    const int gid  = lane >> 2;         // 0..7
    const int tig  = lane & 3;          // 0..3

    const int m0    = blockIdx.x * BM;
    const int nglob = blockIdx.y * BN;
    int e = 0, nb;
    if (B3D) { e = nglob >> 11; nb = nglob & (GUP - 1); }
    else     { nb = nglob; }

    if (tid == 0) {
        #pragma unroll
        for (int i = 0; i < 4; i++) MBAR_INIT(sb + SMEM_MBAR + i * 8, 1);
    }
    __syncthreads();

    auto issue = [&](int s) {
        int b = s & 3, k0 = s * BK;
        uint32_t mb  = sb + SMEM_MBAR + b * 8;
        uint32_t dst = sb + SMEM_DATA + b * STG_BYTES;
        MBAR_EXPECT_TX(mb, STG_BYTES);
        TMA2D(dst, &mA, k0, m0, mb);                 // A [128m x 32k]
        if (B3D) TMA3D(dst + A_BYTES, &mB, k0, nb, e, mb);   // B [256n x 32k], n-major
        else     TMA2D(dst + A_BYTES, &mB, k0, nb, mb);
    };

    if (tid == 0) { issue(0); issue(1); issue(2); }

    float acc[4][8][4];
    #pragma unroll
    for (int i = 0; i < 4; i++)
        #pragma unroll
        for (int j = 0; j < 8; j++)
            #pragma unroll
            for (int r = 0; r < 4; r++) acc[i][j][r] = 0.0f;

    // ldmatrix per-thread addressing (swizzle xor is per-thread constant)
    const uint32_t swz   = (uint32_t)(lane & 7) << 4;            // (row&7)*16
    const int      arow  = lane & 15;                            // A row within 16
    const uint32_t agran = (uint32_t)(lane >> 4);                // A k-granule half (0/1)
    const int      brow  = (lane & 7) + ((lane >> 4) << 3);      // B row within 16
    const uint32_t bgran = (uint32_t)((lane >> 3) & 1);          // B k-granule half (0/1)

    #pragma unroll 1
    for (int kt = 0; kt < KT; kt++) {
        int b = kt & 3;
        MBAR_WAIT(sb + SMEM_MBAR + b * 8, (kt >> 2) & 1);
        __syncthreads();                          // prior stage fully consumed
        if (tid == 0 && kt + 3 < KT) issue(kt + 3);

        uint32_t sA = sb + SMEM_DATA + b * STG_BYTES;
        uint32_t sB = sA + A_BYTES;

        uint32_t aBase[4], bBase[4];
        #pragma unroll
        for (int mf = 0; mf < 4; mf++) aBase[mf] = sA + (uint32_t)((mw + mf * 16 + arow) * 128);
        #pragma unroll
        for (int np = 0; np < 4; np++) bBase[np] = sB + (uint32_t)((nw + np * 16 + brow) * 128);

        #pragma unroll
        for (int ks = 0; ks < 4; ks++) {
            const uint32_t aOff = (((uint32_t)(2 * ks) + agran) << 4) ^ swz;
            const uint32_t bOff = (((uint32_t)(2 * ks) + bgran) << 4) ^ swz;
            uint32_t a[4][4];
            #pragma unroll
            for (int mf = 0; mf < 4; mf++)
                LDSM4(a[mf][0], a[mf][1], a[mf][2], a[mf][3], aBase[mf] + aOff);
            uint32_t bf[8][2];
            #pragma unroll
            for (int np = 0; np < 4; np++)
                LDSM4(bf[2 * np][0], bf[2 * np][1], bf[2 * np + 1][0], bf[2 * np + 1][1],
                      bBase[np] + bOff);
            #pragma unroll
            for (int mf = 0; mf < 4; mf++)
                #pragma unroll
                for (int nf = 0; nf < 8; nf++)
                    mma8(acc[mf][nf], a[mf], bf[nf]);
        }
    }

    // ===================== epilogue =====================
    if (EPI == 1) {
        #pragma unroll
        for (int mf = 0; mf < 4; mf++) {
            #pragma unroll
            for (int h = 0; h < 2; h++) {
                int t = m0 + mw + mf * 16 + h * 8 + gid;
                float rwv = rw[t * NEXP + e];
                float* actp = outp + (size_t)t * KTOT + e * 1024;
                #pragma unroll
                for (int nf = 0; nf < 8; nf++) {
                    int gcol = nb + nw + nf * 8 + 2 * tig;   // even = gate, odd = up
                    float2 bv = *(const float2*)(b1 + e * GUP + gcol);
                    float g = acc[mf][nf][h * 2 + 0] + bv.x;
                    float u = acc[mf][nf][h * 2 + 1] + bv.y;
                    g = fminf(g, 7.0f);
                    u = fminf(fmaxf(u, -7.0f), 7.0f);
                    float glu = g / (1.0f + __expf(-1.702f * g));
                    actp[gcol >> 1] = tf32_rn((u + 1.0f) * glu * rwv);
                }
            }
        }
    } else {
        #pragma unroll
        for (int mf = 0; mf < 4; mf++) {
            #pragma unroll
            for (int h = 0; h < 2; h++) {
                int t = m0 + mw + mf * 16 + h * 8 + gid;
                const float* bp = bias2 + (size_t)t * HID + nglob;
                float* op = outp + (size_t)t * HID + nglob;
                #pragma unroll
                for (int nf = 0; nf < 8; nf++) {
                    int n = nw + nf * 8 + 2 * tig;
                    float2 bv = *(const float2*)(bp + n);
                    float2 ov;
                    ov.x = acc[mf][nf][h * 2 + 0] + bv.x;
                    ov.y = acc[mf][nf][h * 2 + 1] + bv.y;
                    *(float2*)(op + n) = ov;
                }
            }
        }
    }
}

// ===================== prep kernels =====================
__global__ void round_x_kernel(const float4* __restrict__ in, float4* __restrict__ out, int n4) {
    int i = blockIdx.x * 256 + threadIdx.x;
    if (i < n4) {
        float4 v = in[i];
        v.x = tf32_rn(v.x); v.y = tf32_rn(v.y); v.z = tf32_rn(v.z); v.w = tf32_rn(v.w);
        out[i] = v;
    }
}

// in: [z][R][C] -> out: [z][C][R], tf32-rounded
__global__ void transpose_round_kernel(const float* __restrict__ in, float* __restrict__ out,
                                       int R, int C) {
    __shared__ float tile[32][33];
    size_t base = (size_t)blockIdx.z * (size_t)R * C;
    const float* ip = in + base;
    float* op = out + base;
    int c0 = blockIdx.x * 32, r0 = blockIdx.y * 32;
    #pragma unroll
    for (int j = 0; j < 4; j++) {
        int r = r0 + threadIdx.y + j * 8;
        tile[threadIdx.y + j * 8][threadIdx.x] = ip[(size_t)r * C + c0 + threadIdx.x];
    }
    __syncthreads();
    #pragma unroll
    for (int j = 0; j < 4; j++) {
        int c = c0 + threadIdx.y + j * 8;
        op[(size_t)c * R + r0 + threadIdx.x] = tf32_rn(tile[threadIdx.x][threadIdx.y + j * 8]);
    }
}

__global__ void bias2_kernel(const float* __restrict__ rw,
                             const float* __restrict__ b2,
                             float* __restrict__ bias2) {
    int h = blockIdx.x * 256 + threadIdx.x;
    int t = blockIdx.y;
    float s = 0.0f;
    #pragma unroll
    for (int e = 0; e < NEXP; e++) s += rw[t * NEXP + e] * b2[e * HID + h];
    bias2[(size_t)t * HID + h] = s;
}

// ===================== host side =====================
typedef CUresult (CUDAAPI *PFN_encodeTiled)(
    CUtensorMap*, CUtensorMapDataType, cuuint32_t, void*,
    const cuuint64_t*, const cuuint64_t*, const cuuint32_t*, const cuuint32_t*,
    CUtensorMapInterleave, CUtensorMapSwizzle, CUtensorMapL2promotion, CUtensorMapFloatOOBfill);

static PFN_encodeTiled get_encode_fn() {
    void* fp = nullptr;
    cudaDriverEntryPointQueryResult qr;
#if CUDART_VERSION >= 12050
    cudaGetDriverEntryPointByVersion("cuTensorMapEncodeTiled", &fp, 12000, cudaEnableDefault, &qr);
#else
    cudaGetDriverEntryPoint("cuTensorMapEncodeTiled", &fp, cudaEnableDefault, &qr);
#endif
    return (PFN_encodeTiled)fp;
}

static CUtensorMap make_map(PFN_encodeTiled enc, void* p, int nd,
                            uint64_t d0, uint64_t d1, uint64_t d2,
                            uint32_t b0, uint32_t b1) {
    CUtensorMap m;
    cuuint64_t dims[3]    = {d0, d1, d2};
    cuuint64_t strides[2] = {d0 * 4, d0 * d1 * 4};
    cuuint32_t box[3]     = {b0, b1, 1};
    cuuint32_t es[3]      = {1, 1, 1};
    enc(&m, CU_TENSOR_MAP_DATA_TYPE_FLOAT32, nd, p, dims, strides, box, es,
        CU_TENSOR_MAP_INTERLEAVE_NONE, CU_TENSOR_MAP_SWIZZLE_128B,
        CU_TENSOR_MAP_L2_PROMOTION_L2_128B, CU_TENSOR_MAP_FLOAT_OOB_FILL_NONE);
    return m;
}

extern "C" void kernel_launch(void* const* d_in, const int* in_sizes, int n_in,
                              void* d_out, int out_size) {
    const float* X  = (const float*)d_in[0];  // [4096][1024]
    const float* RW = (const float*)d_in[1];  // [4096][8]
    const float* W1 = (const float*)d_in[2];  // [8][1024][2048]  (h, g)
    const float* B1 = (const float*)d_in[3];  // [8][2048]
    const float* W2 = (const float*)d_in[4];  // [8][1024][1024]  (flat: [8192 k][1024 h])
    const float* B2 = (const float*)d_in[5];  // [8][1024]
    float* OUT = (float*)d_out;

    float *ACT, *BIAS2, *XR, *W1T, *W2T;
    cudaGetSymbolAddress((void**)&ACT,   g_ACT);
    cudaGetSymbolAddress((void**)&BIAS2, g_BIAS2);
    cudaGetSymbolAddress((void**)&XR,    g_XR);
    cudaGetSymbolAddress((void**)&W1T,   g_W1T);
    cudaGetSymbolAddress((void**)&W2T,   g_W2T);

    PFN_encodeTiled enc = get_encode_fn();
    // A1: Xr [4096 t][1024 k], box {32k, 128m}
    CUtensorMap mA1 = make_map(enc, XR,  2, HID,  TOKENS, 1,    BK, BM);
    // B1: W1T [8 e][2048 n][1024 k], box {32k, 256n}
    CUtensorMap mB1 = make_map(enc, W1T, 3, HID,  GUP,    NEXP, BK, BN);
    // A2: ACT [4096 t][8192 k], box {32k, 128m}
    CUtensorMap mA2 = make_map(enc, ACT, 2, KTOT, TOKENS, 1,    BK, BM);
    // B2: W2T [1024 n][8192 k], box {32k, 256n}
    CUtensorMap mB2 = make_map(enc, W2T, 2, KTOT, HID,    1,    BK, BN);

    cudaFuncSetAttribute((const void*)gemm_kernel<HID/BK,  true,  1>,
                         cudaFuncAttributeMaxDynamicSharedMemorySize, SMEM_TOTAL);
    cudaFuncSetAttribute((const void*)gemm_kernel<KTOT/BK, false, 2>,
                         cudaFuncAttributeMaxDynamicSharedMemorySize, SMEM_TOTAL);

    // prep
    round_x_kernel<<<TOKENS * HID / 4 / 256, 256>>>((const float4*)X, (float4*)XR, TOKENS * HID / 4);
    bias2_kernel<<<dim3(HID / 256, TOKENS), 256>>>(RW, B2, BIAS2);
    // W1 [e][1024 h][2048 g] -> W1T [e][2048 g][1024 h]
    transpose_round_kernel<<<dim3(GUP / 32, HID / 32, NEXP), dim3(32, 8)>>>(W1, W1T, HID, GUP);
    // W2 flat [8192 k][1024 h] -> W2T [1024 h][8192 k]
    transpose_round_kernel<<<dim3(HID / 32, KTOT / 32, 1), dim3(32, 8)>>>(W2, W2T, KTOT, HID);

    // GEMM1: [4096 x 16384], K=1024
    gemm_kernel<HID/BK, true, 1><<<dim3(TOKENS / BM, (NEXP * GUP) / BN), THREADS, SMEM_TOTAL>>>(
        mA1, mB1, B1, RW, nullptr, ACT);

    // GEMM2: [4096 x 1024], K=8192
    gemm_kernel<KTOT/BK, false, 2><<<dim3(TOKENS / BM, HID / BN), THREADS, SMEM_TOTAL>>>(
        mA2, mB2, nullptr, nullptr, BIAS2, OUT);
}

// round 14
// speedup vs baseline: 1.2716x; 1.0994x over previous
#include <cuda_runtime.h>
#include <cuda_bf16.h>
#include <cuda.h>
#include <cstdint>
#include <cstddef>

// ===================== problem constants =====================
#define TOKENS 4096
#define HID    1024
#define NEXP   8
#define GUP    2048
#define KTOT   8192          // NEXP*1024

// ===================== GEMM tiling =====================
#define BM     128
#define BN     256
#define BK     32
#define THREADS 256          // 8 warps: 2 (M) x 4 (N), warp tile 64x64

#define A_BYTES   16384      // 128 rows x 128B (32k)
#define B_BYTES   32768      // 256 n-rows x 128B (32k)   [N-major!]
#define STG_BYTES (A_BYTES + B_BYTES)   // 49152
#define SMEM_FULL  0          // 4 x 8B
#define SMEM_EMPTY 32         // 4 x 8B
#define SMEM_DATA  1024
#define SMEM_TOTAL (SMEM_DATA + 4*STG_BYTES)   // 197632

// ===================== device scratch =====================
__device__ __align__(1024) float g_ACT  [(size_t)TOKENS*KTOT];  // 128 MB (tf32-rounded)
__device__ __align__(1024) float g_BIAS2[(size_t)TOKENS*HID];   // 16 MB
__device__ __align__(1024) float g_XR   [(size_t)TOKENS*HID];   // 16 MB (tf32-rounded X)
__device__ __align__(1024) float g_W1T  [(size_t)NEXP*GUP*HID]; // 64 MB  [e][g][h] (n-major)
__device__ __align__(1024) float g_W2T  [(size_t)HID*KTOT];     // 32 MB  [h][e*1024+d] (n-major)

// ===================== PTX helpers =====================
__device__ __forceinline__ uint32_t smem_u32(const void* p) {
    uint32_t a;
    asm("{ .reg .u64 t; cvta.to.shared.u64 t, %1; cvt.u32.u64 %0, t; }" : "=r"(a) : "l"(p));
    return a;
}
__device__ __forceinline__ float tf32_rn(float x) {
    uint32_t u;
    asm("cvt.rna.tf32.f32 %0, %1;" : "=r"(u) : "f"(x));
    return __uint_as_float(u);
}
__device__ __forceinline__ void mma8(float* c, const uint32_t* a, const uint32_t* b) {
    asm volatile(
        "mma.sync.aligned.m16n8k8.row.col.f32.tf32.tf32.f32 "
        "{%0,%1,%2,%3}, {%4,%5,%6,%7}, {%8,%9}, {%0,%1,%2,%3};"
        : "+f"(c[0]), "+f"(c[1]), "+f"(c[2]), "+f"(c[3])
        : "r"(a[0]), "r"(a[1]), "r"(a[2]), "r"(a[3]), "r"(b[0]), "r"(b[1]));
}
#define LDSM4(r0, r1, r2, r3, addr) \
    asm volatile("ldmatrix.sync.aligned.m8n8.x4.shared.b16 {%0,%1,%2,%3}, [%4];" \
        : "=r"(r0), "=r"(r1), "=r"(r2), "=r"(r3) : "r"(addr))

#define MBAR_INIT(addr, cnt) \
    asm volatile("mbarrier.init.shared.b64 [%0], %1;" :: "r"((uint32_t)(addr)), "r"((uint32_t)(cnt)) : "memory")
#define MBAR_EXPECT_TX(addr, bytes) \
    asm volatile("mbarrier.arrive.expect_tx.shared.b64 _, [%0], %1;" :: "r"((uint32_t)(addr)), "r"((uint32_t)(bytes)) : "memory")
#define MBAR_ARRIVE(addr) \
    asm volatile("mbarrier.arrive.release.cta.shared.b64 _, [%0];" :: "r"((uint32_t)(addr)) : "memory")

#define MBAR_WAIT(addr, parity) do {                                                    \
    uint32_t _m = (uint32_t)(addr), _p = (uint32_t)(parity), _d;                        \
    asm volatile("{\n\t.reg .pred p;\n\t"                                               \
        "mbarrier.try_wait.parity.acquire.cta.shared::cta.b64 p, [%1], %2;\n\t"         \
        "selp.b32 %0, 1, 0, p;\n\t}" : "=r"(_d) : "r"(_m), "r"(_p) : "memory");         \
    if (!_d) {                                                                          \
        asm volatile("{\n\t.reg .pred P1;\n\t"                                          \
            "WLA_%=:\n\t"                                                               \
            "mbarrier.try_wait.parity.acquire.cta.shared::cta.b64 P1, [%0], %1, 0x989680;\n\t" \
            "@P1 bra.uni WDA_%=;\n\t"                                                   \
            "bra.uni WLA_%=;\n\t"                                                       \
            "WDA_%=:\n\t}" :: "r"(_m), "r"(_p) : "memory");                             \
    }                                                                                   \
} while (0)

#define TMA2D(smem_addr, tmap, cx, cy, mbar) \
    asm volatile("cp.async.bulk.tensor.2d.shared::cta.global.tile.mbarrier::complete_tx::bytes " \
        "[%0], [%1, {%2, %3}], [%4];" \
        :: "r"((uint32_t)(smem_addr)), "l"(tmap), "r"((int32_t)(cx)), "r"((int32_t)(cy)), \
           "r"((uint32_t)(mbar)) : "memory")
#define TMA3D(smem_addr, tmap, cx, cy, cz, mbar) \
    asm volatile("cp.async.bulk.tensor.3d.shared::cta.global.tile.mbarrier::complete_tx::bytes " \
        "[%0], [%1, {%2, %3, %4}], [%5];" \
        :: "r"((uint32_t)(smem_addr)), "l"(tmap), "r"((int32_t)(cx)), "r"((int32_t)(cy)), \
           "r"((int32_t)(cz)), "r"((uint32_t)(mbar)) : "memory")

// ===================== fused GEMM kernel =====================
// A smem: [128 m-rows][32 k], 128B rows, SW128.
// B smem: [256 n-rows][32 k], 128B rows, SW128 (N-MAJOR -> natural ldmatrix B frag).
// Full/empty mbarrier pairs per stage (CUTLASS pattern): consumers gated only
// by data-readiness; warp0/lane0 waits each stage's empty barrier (count 8,
// phase parity) before re-issuing TMA. Overrun-safe under warp run-ahead.
// EPI=1: GEMM1 -> act epilogue -> ACT (rounded). EPI=2: GEMM2 -> + BIAS2 -> out.
template <int KT, bool B3D, int EPI>
__global__ void __launch_bounds__(THREADS, 1)
gemm_kernel(const __grid_constant__ CUtensorMap mA,
            const __grid_constant__ CUtensorMap mB,
            const float* __restrict__ b1,      // [8][2048]    (EPI=1)
            const float* __restrict__ rw,      // [4096][8]    (EPI=1)
            const float* __restrict__ bias2,   // [4096][1024] (EPI=2)
            float* __restrict__ outp)
{
    extern __shared__ __align__(1024) char smem[];
    uint32_t sb = smem_u32(smem);

    const int tid  = threadIdx.x;
    const int lane = tid & 31;
    const int w    = tid >> 5;          // 0..7
    const int mw   = (w >> 2) * 64;     // warp M offset (0,64)
    const int nw   = (w & 3) * 64;      // warp N offset (0,64,128,192)
    const int gid  = lane >> 2;         // 0..7
    const int tig  = lane & 3;          // 0..3

    const int m0    = blockIdx.x * BM;
    const int nglob = blockIdx.y * BN;
    int e = 0, nb;
    if (B3D) { e = nglob >> 11; nb = nglob & (GUP - 1); }
    else     { nb = nglob; }

    if (tid == 0) {
        #pragma unroll
        for (int i = 0; i < 4; i++) {
            MBAR_INIT(sb + SMEM_FULL  + i * 8, 1);
            MBAR_INIT(sb + SMEM_EMPTY + i * 8, 8);   // one arrive per warp
        }
    }
    __syncthreads();

    auto issue = [&](int s) {
        int b = s & 3, k0 = s * BK;
        uint32_t mb  = sb + SMEM_FULL + b * 8;
        uint32_t dst = sb + SMEM_DATA + b * STG_BYTES;
        MBAR_EXPECT_TX(mb, STG_BYTES);
        TMA2D(dst, &mA, k0, m0, mb);                 // A [128m x 32k]
        if (B3D) TMA3D(dst + A_BYTES, &mB, k0, nb, e, mb);   // B [256n x 32k], n-major
        else     TMA2D(dst + A_BYTES, &mB, k0, nb, mb);
    };

    if (tid == 0) { issue(0); issue(1); issue(2); issue(3); }   // fill all 4 stages

    float acc[4][8][4];
    #pragma unroll
    for (int i = 0; i < 4; i++)
        #pragma unroll
        for (int j = 0; j < 8; j++)
            #pragma unroll
            for (int r = 0; r < 4; r++) acc[i][j][r] = 0.0f;

    // ldmatrix per-thread addressing (swizzle xor is per-thread constant)
    const uint32_t swz   = (uint32_t)(lane & 7) << 4;            // (row&7)*16
    const int      arow  = lane & 15;                            // A row within 16
    const uint32_t agran = (uint32_t)(lane >> 4);                // A k-granule half (0/1)
    const int      brow  = (lane & 7) + ((lane >> 4) << 3);      // B row within 16
    const uint32_t bgran = (uint32_t)((lane >> 3) & 1);          // B k-granule half (0/1)

    #pragma unroll 1
    for (int kt = 0; kt < KT; kt++) {
        int b = kt & 3;
        uint32_t fullb  = sb + SMEM_FULL  + b * 8;
        uint32_t emptyb = sb + SMEM_EMPTY + b * 8;
        MBAR_WAIT(fullb, (kt >> 2) & 1);

        uint32_t sA = sb + SMEM_DATA + b * STG_BYTES;
        uint32_t sB = sA + A_BYTES;

        uint32_t aBase[4], bBase[4];
        #pragma unroll
        for (int mf = 0; mf < 4; mf++) aBase[mf] = sA + (uint32_t)((mw + mf * 16 + arow) * 128);
        #pragma unroll
        for (int np = 0; np < 4; np++) bBase[np] = sB + (uint32_t)((nw + np * 16 + brow) * 128);

        #pragma unroll
        for (int ks = 0; ks < 4; ks++) {
            const uint32_t aOff = (((uint32_t)(2 * ks) + agran) << 4) ^ swz;
            const uint32_t bOff = (((uint32_t)(2 * ks) + bgran) << 4) ^ swz;
            uint32_t a[4][4];
            #pragma unroll
            for (int mf = 0; mf < 4; mf++)
                LDSM4(a[mf][0], a[mf][1], a[mf][2], a[mf][3], aBase[mf] + aOff);
            uint32_t bf[8][2];
            #pragma unroll
            for (int np = 0; np < 4; np++)
                LDSM4(bf[2 * np][0], bf[2 * np][1], bf[2 * np + 1][0], bf[2 * np + 1][1],
                      bBase[np] + bOff);
            #pragma unroll
            for (int mf = 0; mf < 4; mf++)
                #pragma unroll
                for (int nf = 0; nf < 8; nf++)
                    mma8(acc[mf][nf], a[mf], bf[nf]);
        }

        // done reading stage b: elected per-warp arrive (release)
        __syncwarp();
        if (lane == 0) {
            MBAR_ARRIVE(emptyb);
            if (w == 0 && kt + 4 < KT) {
                // wait until ALL warps (incl. this one) finished round kt on stage b
                MBAR_WAIT(emptyb, (kt >> 2) & 1);
                issue(kt + 4);
            }
        }
    }

    // ===================== epilogue =====================
    if (EPI == 1) {
        #pragma unroll
        for (int mf = 0; mf < 4; mf++) {
            #pragma unroll
            for (int h = 0; h < 2; h++) {
                int t = m0 + mw + mf * 16 + h * 8 + gid;
                float rwv = rw[t * NEXP + e];
                float* actp = outp + (size_t)t * KTOT + e * 1024;
                #pragma unroll
                for (int nf = 0; nf < 8; nf++) {
                    int gcol = nb + nw + nf * 8 + 2 * tig;   // even = gate, odd = up
                    float2 bv = *(const float2*)(b1 + e * GUP + gcol);
                    float g = acc[mf][nf][h * 2 + 0] + bv.x;
                    float u = acc[mf][nf][h * 2 + 1] + bv.y;
                    g = fminf(g, 7.0f);
                    u = fminf(fmaxf(u, -7.0f), 7.0f);
                    float glu = g / (1.0f + __expf(-1.702f * g));
                    actp[gcol >> 1] = tf32_rn((u + 1.0f) * glu * rwv);
                }
            }
        }
    } else {
        #pragma unroll
        for (int mf = 0; mf < 4; mf++) {
            #pragma unroll
            for (int h = 0; h < 2; h++) {
                int t = m0 + mw + mf * 16 + h * 8 + gid;
                const float* bp = bias2 + (size_t)t * HID + nglob;
                float* op = outp + (size_t)t * HID + nglob;
                #pragma unroll
                for (int nf = 0; nf < 8; nf++) {
                    int n = nw + nf * 8 + 2 * tig;
                    float2 bv = *(const float2*)(bp + n);
                    float2 ov;
                    ov.x = acc[mf][nf][h * 2 + 0] + bv.x;
                    ov.y = acc[mf][nf][h * 2 + 1] + bv.y;
                    *(float2*)(op + n) = ov;
                }
            }
        }
    }
}

// ===================== prep kernels =====================
__global__ void round_x_kernel(const float4* __restrict__ in, float4* __restrict__ out, int n4) {
    int i = blockIdx.x * 256 + threadIdx.x;
    if (i < n4) {
        float4 v = in[i];
        v.x = tf32_rn(v.x); v.y = tf32_rn(v.y); v.z = tf32_rn(v.z); v.w = tf32_rn(v.w);
        out[i] = v;
    }
}

// in: [z][R][C] -> out: [z][C][R], tf32-rounded
__global__ void transpose_round_kernel(const float* __restrict__ in, float* __restrict__ out,
                                       int R, int C) {
    __shared__ float tile[32][33];
    size_t base = (size_t)blockIdx.z * (size_t)R * C;
    const float* ip = in + base;
    float* op = out + base;
    int c0 = blockIdx.x * 32, r0 = blockIdx.y * 32;
    #pragma unroll
    for (int j = 0; j < 4; j++) {
        int r = r0 + threadIdx.y + j * 8;
        tile[threadIdx.y + j * 8][threadIdx.x] = ip[(size_t)r * C + c0 + threadIdx.x];
    }
    __syncthreads();
    #pragma unroll
    for (int j = 0; j < 4; j++) {
        int c = c0 + threadIdx.y + j * 8;
        op[(size_t)c * R + r0 + threadIdx.x] = tf32_rn(tile[threadIdx.x][threadIdx.y + j * 8]);
    }
}

__global__ void bias2_kernel(const float* __restrict__ rw,
                             const float* __restrict__ b2,
                             float* __restrict__ bias2) {
    int h = blockIdx.x * 256 + threadIdx.x;
    int t = blockIdx.y;
    float s = 0.0f;
    #pragma unroll
    for (int e = 0; e < NEXP; e++) s += rw[t * NEXP + e] * b2[e * HID + h];
    bias2[(size_t)t * HID + h] = s;
}

// ===================== host side =====================
typedef CUresult (CUDAAPI *PFN_encodeTiled)(
    CUtensorMap*, CUtensorMapDataType, cuuint32_t, void*,
    const cuuint64_t*, const cuuint64_t*, const cuuint32_t*, const cuuint32_t*,
    CUtensorMapInterleave, CUtensorMapSwizzle, CUtensorMapL2promotion, CUtensorMapFloatOOBfill);

static PFN_encodeTiled get_encode_fn() {
    void* fp = nullptr;
    cudaDriverEntryPointQueryResult qr;
#if CUDART_VERSION >= 12050
    cudaGetDriverEntryPointByVersion("cuTensorMapEncodeTiled", &fp, 12000, cudaEnableDefault, &qr);
#else
    cudaGetDriverEntryPoint("cuTensorMapEncodeTiled", &fp, cudaEnableDefault, &qr);
#endif
    return (PFN_encodeTiled)fp;
}

static CUtensorMap make_map(PFN_encodeTiled enc, void* p, int nd,
                            uint64_t d0, uint64_t d1, uint64_t d2,
                            uint32_t b0, uint32_t b1) {
    CUtensorMap m;
    cuuint64_t dims[3]    = {d0, d1, d2};
    cuuint64_t strides[2] = {d0 * 4, d0 * d1 * 4};
    cuuint32_t box[3]     = {b0, b1, 1};
    cuuint32_t es[3]      = {1, 1, 1};
    enc(&m, CU_TENSOR_MAP_DATA_TYPE_FLOAT32, nd, p, dims, strides, box, es,
        CU_TENSOR_MAP_INTERLEAVE_NONE, CU_TENSOR_MAP_SWIZZLE_128B,
        CU_TENSOR_MAP_L2_PROMOTION_L2_128B, CU_TENSOR_MAP_FLOAT_OOB_FILL_NONE);
    return m;
}

extern "C" void kernel_launch(void* const* d_in, const int* in_sizes, int n_in,
                              void* d_out, int out_size) {
    const float* X  = (const float*)d_in[0];  // [4096][1024]
    const float* RW = (const float*)d_in[1];  // [4096][8]
    const float* W1 = (const float*)d_in[2];  // [8][1024][2048]  (h, g)
    const float* B1 = (const float*)d_in[3];  // [8][2048]
    const float* W2 = (const float*)d_in[4];  // [8][1024][1024]  (flat: [8192 k][1024 h])
    const float* B2 = (const float*)d_in[5];  // [8][1024]
    float* OUT = (float*)d_out;

    float *ACT, *BIAS2, *XR, *W1T, *W2T;
    cudaGetSymbolAddress((void**)&ACT,   g_ACT);
    cudaGetSymbolAddress((void**)&BIAS2, g_BIAS2);
    cudaGetSymbolAddress((void**)&XR,    g_XR);
    cudaGetSymbolAddress((void**)&W1T,   g_W1T);
    cudaGetSymbolAddress((void**)&W2T,   g_W2T);

    PFN_encodeTiled enc = get_encode_fn();
    // A1: Xr [4096 t][1024 k], box {32k, 128m}
    CUtensorMap mA1 = make_map(enc, XR,  2, HID,  TOKENS, 1,    BK, BM);
    // B1: W1T [8 e][2048 n][1024 k], box {32k, 256n}
    CUtensorMap mB1 = make_map(enc, W1T, 3, HID,  GUP,    NEXP, BK, BN);
    // A2: ACT [4096 t][8192 k], box {32k, 128m}
    CUtensorMap mA2 = make_map(enc, ACT, 2, KTOT, TOKENS, 1,    BK, BM);
    // B2: W2T [1024 n][8192 k], box {32k, 256n}
    CUtensorMap mB2 = make_map(enc, W2T, 2, KTOT, HID,    1,    BK, BN);

    cudaFuncSetAttribute((const void*)gemm_kernel<HID/BK,  true,  1>,
                         cudaFuncAttributeMaxDynamicSharedMemorySize, SMEM_TOTAL);
    cudaFuncSetAttribute((const void*)gemm_kernel<KTOT/BK, false, 2>,
                         cudaFuncAttributeMaxDynamicSharedMemorySize, SMEM_TOTAL);

    // prep
    round_x_kernel<<<TOKENS * HID / 4 / 256, 256>>>((const float4*)X, (float4*)XR, TOKENS * HID / 4);
    bias2_kernel<<<dim3(HID / 256, TOKENS), 256>>>(RW, B2, BIAS2);
    // W1 [e][1024 h][2048 g] -> W1T [e][2048 g][1024 h]
    transpose_round_kernel<<<dim3(GUP / 32, HID / 32, NEXP), dim3(32, 8)>>>(W1, W1T, HID, GUP);
    // W2 flat [8192 k][1024 h] -> W2T [1024 h][8192 k]
    transpose_round_kernel<<<dim3(HID / 32, KTOT / 32, 1), dim3(32, 8)>>>(W2, W2T, KTOT, HID);

    // GEMM1: [4096 x 16384], K=1024
    gemm_kernel<HID/BK, true, 1><<<dim3(TOKENS / BM, (NEXP * GUP) / BN), THREADS, SMEM_TOTAL>>>(
        mA1, mB1, B1, RW, nullptr, ACT);

    // GEMM2: [4096 x 1024], K=8192
    gemm_kernel<KTOT/BK, false, 2><<<dim3(TOKENS / BM, HID / BN), THREADS, SMEM_TOTAL>>>(
        mA2, mB2, nullptr, nullptr, BIAS2, OUT);
}